// round 15
// baseline (speedup 1.0000x reference)
#include <cuda_runtime.h>
#include <cuda_fp16.h>
#include <math.h>

#define NN   50000
#define EE   800000
#define FIN  32
#define HH   64
#define H2   128
#define EDIM 16
#define GG   64
#define COUT 40
#define PCHUNK 64
#define HIST_BLKS 782
#define LIN_BLKS 782        // 64-node tiles
#define ZBLKS 782           // embgemm blocks that also do the l=1 z-pass
#define SCAN_BLKS 49

typedef unsigned long long u64;
typedef unsigned int u32;

#define FMA2(acc, a, b) asm("fma.rn.f32x2 %0, %1, %2, %0;" : "+l"(acc) : "l"(a), "l"(b))
#define PACK2(d, lo, hi) asm("mov.b64 %0, {%1, %2};" : "=l"(d) : "r"(lo), "r"(hi))
#define UNPACK2(lo, hi, s) asm("mov.b64 {%0, %1}, %2;" : "=r"(lo), "=r"(hi) : "l"(s))

// ---------------- scratch (no allocation allowed) ----------------
// All mutable state is returned to zero by tail kernels (k_pool/k_final).
__device__ float g_h[NN * HH];      // node features (residual stream)
__device__ float g_z[NN * HH];      // relu(BN(h)) for current layer
__device__ float g_hmid[NN * H2];   // MLP hidden
__device__ float g_sA[3][HH];
__device__ float g_qA[3][HH];
__device__ float g_sB[2][H2];
__device__ float g_qB[2][H2];
__device__ float g_pool[GG * HH];
__device__ float g_cnt[GG];
// CSR scratch
__device__ int g_deg[NN];
__device__ int g_cur[NN];           // seeded with offsets by k_scan
__device__ int g_off[NN + 1];
__device__ int g_psrc[EE];
__device__ int g_perm[EE];          // edge e -> CSR slot (written by embgemm l=0)
__device__ u32 g_embh[(size_t)EE * 32];      // current layer's edge emb (CSR order), half2
__device__ u64 g_look[64];

// -------- merged: degree histogram (blocks [0,782)) + input linear ---------
// linear part: f32x2 register-tiled GEMM h = x @ W_in + b, fused statsA(0)
__global__ void k_histlin(const int* __restrict__ ei,
                          const float* __restrict__ x,
                          const float* __restrict__ W,
                          const float* __restrict__ b) {
    __shared__ float xs[FIN * 68];        // transposed [k][node], pad 68
    __shared__ float sred[16][HH];        // 4KB
    int tid = threadIdx.x;

    if (blockIdx.x < HIST_BLKS) {         // ---- histogram part ----
        int t = blockIdx.x * 256 + tid;
        if (t * 4 < EE) {
            int4 d4 = ((const int4*)(ei + EE))[t];
            atomicAdd(&g_deg[d4.x], 1);
            atomicAdd(&g_deg[d4.y], 1);
            atomicAdd(&g_deg[d4.z], 1);
            atomicAdd(&g_deg[d4.w], 1);
        }
        return;
    }
    // ---- input linear: 64-node tile, f32x2 ----
    int bid = blockIdx.x - HIST_BLKS;
    int n0 = bid * 64;
    for (int idx = tid; idx < 64 * 8; idx += 256) {
        int r = idx >> 3, q = idx & 7;
        int gn = n0 + r;
        float4 v = (gn < NN) ? ((const float4*)(x + (size_t)gn * FIN))[q]
                             : make_float4(0.f, 0.f, 0.f, 0.f);
        xs[(q * 4 + 0) * 68 + r] = v.x;
        xs[(q * 4 + 1) * 68 + r] = v.y;
        xs[(q * 4 + 2) * 68 + r] = v.z;
        xs[(q * 4 + 3) * 68 + r] = v.w;
    }
    __syncthreads();
    int tx = tid & 15, ty = tid >> 4;     // col quarter (16), row group (16)
    int col = tx * 4, row0 = ty * 4;
    u64 acc[2][4];
#pragma unroll
    for (int p = 0; p < 2; p++)
#pragma unroll
        for (int c = 0; c < 4; c++) acc[p][c] = 0ull;
#pragma unroll 4
    for (int k = 0; k < FIN; k++) {
        ulonglong2 ap = *(const ulonglong2*)&xs[k * 68 + row0];
        float4 wv = *(const float4*)&W[k * HH + col];
#pragma unroll
        for (int c = 0; c < 4; c++) {
            u32 wb = __float_as_uint(((const float*)&wv)[c]);
            u64 wd; PACK2(wd, wb, wb);
            FMA2(acc[0][c], ap.x, wd);
            FMA2(acc[1][c], ap.y, wd);
        }
    }
    float4 bb = *(const float4*)&b[col];
    float s[4] = {0.f, 0.f, 0.f, 0.f}, q[4] = {0.f, 0.f, 0.f, 0.f};
#pragma unroll
    for (int p = 0; p < 2; p++) {
        float o0[4], o1[4];
#pragma unroll
        for (int c = 0; c < 4; c++) {
            u32 l_, h_; UNPACK2(l_, h_, acc[p][c]);
            o0[c] = __uint_as_float(l_) + ((const float*)&bb)[c];
            o1[c] = __uint_as_float(h_) + ((const float*)&bb)[c];
        }
        int na = n0 + row0 + p * 2;
        if (na < NN) {
            *(float4*)&g_h[na * HH + col] = make_float4(o0[0], o0[1], o0[2], o0[3]);
#pragma unroll
            for (int c = 0; c < 4; c++) { s[c] += o0[c]; q[c] += o0[c] * o0[c]; }
        }
        if (na + 1 < NN) {
            *(float4*)&g_h[(na + 1) * HH + col] = make_float4(o1[0], o1[1], o1[2], o1[3]);
#pragma unroll
            for (int c = 0; c < 4; c++) { s[c] += o1[c]; q[c] += o1[c] * o1[c]; }
        }
    }
#pragma unroll
    for (int c = 0; c < 4; c++) sred[ty][col + c] = s[c];
    __syncthreads();
    if (tid < HH) {
        float S = 0.f;
#pragma unroll
        for (int i = 0; i < 16; i++) S += sred[i][tid];
        atomicAdd(&g_sA[0][tid], S);
    }
    __syncthreads();
#pragma unroll
    for (int c = 0; c < 4; c++) sred[ty][col + c] = q[c];
    __syncthreads();
    if (tid < HH) {
        float Q = 0.f;
#pragma unroll
        for (int i = 0; i < 16; i++) Q += sred[i][tid];
        atomicAdd(&g_qA[0][tid], Q);
    }
}

// scan with decoupled lookback; seeds g_cur; then computes z0 = relu(BN(h))
__global__ void k_scan(const float* __restrict__ gamma, const float* __restrict__ beta) {
    __shared__ int sh[1024];
    __shared__ int exc_sh;
    __shared__ float scz[HH], sfz[HH];
    int b = blockIdx.x, t = threadIdx.x;
    int i = b * 1024 + t;
    int v = (i < NN) ? g_deg[i] : 0;
    sh[t] = v;
    __syncthreads();
    for (int off = 1; off < 1024; off <<= 1) {
        int u = (t >= off) ? sh[t - off] : 0;
        __syncthreads();
        sh[t] += u;
        __syncthreads();
    }
    int total = sh[1023];
    if (t == 0) {
        const u64 FA = 1ull << 62, FP = 2ull << 62;
        if (b == 0) {
            atomicExch(&g_look[0], FP | (u32)total);
            exc_sh = 0;
        } else {
            atomicExch(&g_look[b], FA | (u32)total);
            int run = 0, j = b - 1;
            while (1) {
                u64 s = atomicAdd(&g_look[j], 0ull);
                u64 f = s >> 62;
                if (f == 0) continue;
                int val = (int)(s & 0xFFFFFFFFull);
                run += val;
                if (f == 2) break;
                j--;
            }
            atomicExch(&g_look[b], FP | (u32)(run + total));
            exc_sh = run;
        }
    }
    if (t < HH) {           // BN consts for layer 0 (stats ready from histlin)
        float mu = g_sA[0][t] * (1.f / NN);
        float var = g_qA[0][t] * (1.f / NN) - mu * mu;
        float s = gamma[t] * rsqrtf(var + 1e-5f);
        scz[t] = s;
        sfz[t] = beta[t] - mu * s;
    }
    __syncthreads();
    int e = exc_sh;
    if (i < NN) {
        int off = e + sh[t] - v;   // exclusive
        g_off[i] = off;
        g_cur[i] = off;            // seed for bump allocation in embgemm l=0
    }
    if (b == 0 && t == 0) g_off[NN] = EE;
    // z0 pass, float4 grid-stride
    for (int i4 = b * 1024 + t; i4 < NN * HH / 4; i4 += SCAN_BLKS * 1024) {
        int j = (i4 * 4) & 63;
        float4 h4 = ((const float4*)g_h)[i4];
        float4 o;
        o.x = fmaxf(h4.x * scz[j]     + sfz[j],     0.f);
        o.y = fmaxf(h4.y * scz[j + 1] + sfz[j + 1], 0.f);
        o.z = fmaxf(h4.z * scz[j + 2] + sfz[j + 2], 0.f);
        o.w = fmaxf(h4.w * scz[j + 3] + sfz[j + 3], 0.f);
        ((float4*)g_z)[i4] = o;
    }
}

// ------- edge-emb GEMM (+ fused scatter when l==0) -------------------------
// l==0: 64 threads/tile allocate CSR slots (atomicAdd), write psrc & perm
// l==1: reload slots from perm; first ZBLKS blocks also compute z1
__global__ void k_embgemm(const int* __restrict__ ei, const float* __restrict__ ea,
                          const float* __restrict__ W, const float* __restrict__ bias,
                          int l, const float* __restrict__ gamma,
                          const float* __restrict__ beta) {
    __shared__ float As[16 * 68];       // transposed [k][edge], pad 68 (16B aligned)
    __shared__ int idxs[64];
    int tid = threadIdx.x;  // 256
    int e0 = blockIdx.x * 64;
    if (l == 0) {
        if (tid < 64) {                 // ---- fused scatter ----
            int e = e0 + tid;
            int src = __ldg(&ei[e]);
            int d = __ldg(&ei[EE + e]);
            int idx = atomicAdd(&g_cur[d], 1);
            g_psrc[idx] = src;
            g_perm[e] = idx;
            idxs[tid] = idx;
        }
    } else {
        if (tid < 64) idxs[tid] = g_perm[e0 + tid];
    }
    {
        int r = tid >> 2, q = tid & 3;  // 64 edges x 4 quarters
        float4 v = ((const float4*)(ea + (size_t)(e0 + r) * EDIM))[q];
        As[(q * 4 + 0) * 68 + r] = v.x;
        As[(q * 4 + 1) * 68 + r] = v.y;
        As[(q * 4 + 2) * 68 + r] = v.z;
        As[(q * 4 + 3) * 68 + r] = v.w;
    }
    __syncthreads();
    int tx = tid & 15, ty = tid >> 4;   // col quarter, edge group
    int col = tx * 4, row0 = ty * 4;
    u64 acc[2][4];
#pragma unroll
    for (int p = 0; p < 2; p++)
#pragma unroll
        for (int c = 0; c < 4; c++) acc[p][c] = 0ull;
#pragma unroll
    for (int k = 0; k < EDIM; k++) {
        ulonglong2 ap = *(const ulonglong2*)&As[k * 68 + row0];  // LDS.128
        float4 wv = *(const float4*)&W[k * HH + col];
#pragma unroll
        for (int c = 0; c < 4; c++) {
            u32 wb = __float_as_uint(((const float*)&wv)[c]);
            u64 wd; PACK2(wd, wb, wb);
            FMA2(acc[0][c], ap.x, wd);
            FMA2(acc[1][c], ap.y, wd);
        }
    }
    float4 bb = *(const float4*)&bias[col];
    int dst[4] = {idxs[row0], idxs[row0 + 1], idxs[row0 + 2], idxs[row0 + 3]};
#pragma unroll
    for (int p = 0; p < 2; p++) {
        float lo[4], hi[4];
#pragma unroll
        for (int c = 0; c < 4; c++) {
            u32 l_, h_; UNPACK2(l_, h_, acc[p][c]);
            lo[c] = __uint_as_float(l_) + ((const float*)&bb)[c];
            hi[c] = __uint_as_float(h_) + ((const float*)&bb)[c];
        }
        __half2 a01 = __floats2half2_rn(lo[0], lo[1]);
        __half2 a23 = __floats2half2_rn(lo[2], lo[3]);
        u64 w0; PACK2(w0, *(u32*)&a01, *(u32*)&a23);
        ((u64*)(g_embh + (size_t)dst[p * 2] * 32))[tx] = w0;
        __half2 b01 = __floats2half2_rn(hi[0], hi[1]);
        __half2 b23 = __floats2half2_rn(hi[2], hi[3]);
        u64 w1; PACK2(w1, *(u32*)&b01, *(u32*)&b23);
        ((u64*)(g_embh + (size_t)dst[p * 2 + 1] * 32))[tx] = w1;
    }
    // ---- z1 pass for layer 1 (uniform per-block condition) ----
    if (l == 1 && blockIdx.x < ZBLKS) {
        __shared__ float scz[HH], sfz[HH];
        if (tid < HH) {
            float mu = g_sA[1][tid] * (1.f / NN);
            float var = g_qA[1][tid] * (1.f / NN) - mu * mu;
            float s = gamma[tid] * rsqrtf(var + 1e-5f);
            scz[tid] = s;
            sfz[tid] = beta[tid] - mu * s;
        }
        __syncthreads();
        int n0z = blockIdx.x * 64;
        for (int idx = tid; idx < 64 * 16; idx += 256) {
            int r = idx >> 4, c4 = (idx & 15) * 4;
            int n = n0z + r;
            if (n < NN) {
                float4 v = *(const float4*)&g_h[n * HH + c4];
                float4 o;
                o.x = fmaxf(v.x * scz[c4]     + sfz[c4],     0.f);
                o.y = fmaxf(v.y * scz[c4 + 1] + sfz[c4 + 1], 0.f);
                o.z = fmaxf(v.z * scz[c4 + 2] + sfz[c4 + 2], 0.f);
                o.w = fmaxf(v.w * scz[c4 + 3] + sfz[c4 + 3], 0.f);
                *(float4*)&g_z[n * HH + c4] = o;
            }
        }
    }
}

// ------- merged gather + MLP1: agg staged in shared, then f32x2 GEMM -------
// 64-node tile, 256 thr. Phase 1: 8 warps x 8 nodes batched gather -> As.
// Phase 2: g_hmid = As^T @ w1 + b1 with statsB epilogue.
__global__ void k_gathermlp1(const float* __restrict__ tptr,
                             const float* __restrict__ w1,
                             const float* __restrict__ b1, int l) {
    __shared__ float As[64 * 66];       // transposed [feature][node]
    __shared__ float sred[8][H2];
    int tid = threadIdx.x;  // 256
    int lane = tid & 31, wid = tid >> 5;
    int n0 = blockIdx.x * 64;
    float tc2 = tptr[0] * 1.4426950408889634f;
    int j0 = lane * 2;
    // ---- gather phase ----
#pragma unroll
    for (int r = 0; r < 8; r++) {
        int nloc = r * 8 + wid;
        int n = n0 + nloc;
        float a0 = 0.f, a1 = 0.f;
        if (n < NN) {
            int beg = g_off[n], end = g_off[n + 1];
            float den0 = 0.f, num0 = 0.f, den1 = 0.f, num1 = 0.f;
            int i = beg;
            for (; i + 8 <= end; i += 8) {
                int srcs[8]; u32 ehb[8];
#pragma unroll
                for (int u = 0; u < 8; u++) srcs[u] = g_psrc[i + u];
#pragma unroll
                for (int u = 0; u < 8; u++) ehb[u] = g_embh[(size_t)(i + u) * 32 + lane];
                float2 zs[8];
#pragma unroll
                for (int u = 0; u < 8; u++) zs[u] = *(const float2*)&g_z[srcs[u] * HH + j0];
#pragma unroll
                for (int u = 0; u < 8; u++) {
                    float2 emb = __half22float2(*(__half2*)&ehb[u]);
                    float m0 = fmaxf(zs[u].x + emb.x, 0.f) + 1e-7f;
                    float m1 = fmaxf(zs[u].y + emb.y, 0.f) + 1e-7f;
                    float ex0 = exp2f(m0 * tc2);   // no max-shift: m in [1e-7, ~6]
                    float ex1 = exp2f(m1 * tc2);
                    den0 += ex0; num0 += ex0 * m0;
                    den1 += ex1; num1 += ex1 * m1;
                }
            }
            for (; i < end; i++) {
                int src = g_psrc[i];
                u32 ehb = g_embh[(size_t)i * 32 + lane];
                float2 emb = __half22float2(*(__half2*)&ehb);
                float2 z = *(const float2*)&g_z[src * HH + j0];
                float m0 = fmaxf(z.x + emb.x, 0.f) + 1e-7f;
                float m1 = fmaxf(z.y + emb.y, 0.f) + 1e-7f;
                float ex0 = exp2f(m0 * tc2);
                float ex1 = exp2f(m1 * tc2);
                den0 += ex0; num0 += ex0 * m0;
                den1 += ex1; num1 += ex1 * m1;
            }
            float2 zr = *(const float2*)&g_z[n * HH + j0];
            a0 = num0 / (den0 + 1e-16f) + zr.x;
            a1 = num1 / (den1 + 1e-16f) + zr.y;
        }
        As[j0 * 66 + nloc] = a0;
        As[(j0 + 1) * 66 + nloc] = a1;
    }
    __syncthreads();
    // ---- GEMM phase (identical to former k_mlp1) ----
    int tx = tid & 31, ty = tid >> 5;
    int col = tx * 4, row0 = ty * 8;
    u64 acc[4][4];
#pragma unroll
    for (int rp = 0; rp < 4; rp++)
#pragma unroll
        for (int c = 0; c < 4; c++) acc[rp][c] = 0ull;
#pragma unroll 4
    for (int k = 0; k < 64; k++) {
        u64 ap[4];
#pragma unroll
        for (int rp = 0; rp < 4; rp++)
            ap[rp] = *(const u64*)&As[k * 66 + row0 + rp * 2];
        float4 wv = *(const float4*)&w1[k * H2 + col];
#pragma unroll
        for (int c = 0; c < 4; c++) {
            u32 wb = __float_as_uint(((const float*)&wv)[c]);
            u64 wd; PACK2(wd, wb, wb);
#pragma unroll
            for (int rp = 0; rp < 4; rp++) FMA2(acc[rp][c], ap[rp], wd);
        }
    }
    float4 bb = *(const float4*)&b1[col];
    float s[4] = {0.f, 0.f, 0.f, 0.f}, q[4] = {0.f, 0.f, 0.f, 0.f};
#pragma unroll
    for (int rp = 0; rp < 4; rp++) {
        float o0[4], o1[4];
#pragma unroll
        for (int c = 0; c < 4; c++) {
            u32 lo, hi; UNPACK2(lo, hi, acc[rp][c]);
            o0[c] = __uint_as_float(lo) + ((const float*)&bb)[c];
            o1[c] = __uint_as_float(hi) + ((const float*)&bb)[c];
        }
        int na = n0 + row0 + rp * 2;
        if (na < NN) {
            *(float4*)&g_hmid[na * H2 + col] = make_float4(o0[0], o0[1], o0[2], o0[3]);
#pragma unroll
            for (int c = 0; c < 4; c++) { s[c] += o0[c]; q[c] += o0[c] * o0[c]; }
        }
        if (na + 1 < NN) {
            *(float4*)&g_hmid[(na + 1) * H2 + col] = make_float4(o1[0], o1[1], o1[2], o1[3]);
#pragma unroll
            for (int c = 0; c < 4; c++) { s[c] += o1[c]; q[c] += o1[c] * o1[c]; }
        }
    }
#pragma unroll
    for (int c = 0; c < 4; c++) sred[ty][col + c] = s[c];
    __syncthreads();
    if (tid < H2) {
        float S = 0.f;
#pragma unroll
        for (int i = 0; i < 8; i++) S += sred[i][tid];
        atomicAdd(&g_sB[l][tid], S);
    }
    __syncthreads();
#pragma unroll
    for (int c = 0; c < 4; c++) sred[ty][col + c] = q[c];
    __syncthreads();
    if (tid < H2) {
        float Q = 0.f;
#pragma unroll
        for (int i = 0; i < 8; i++) Q += sred[i][tid];
        atomicAdd(&g_qB[l][tid], Q);
    }
}

// ------- MLP2 GEMM (128 thr), fused BN2+ReLU staging + residual ------------
__global__ void k_mlp2(const float* __restrict__ w2, const float* __restrict__ b2,
                       const float* __restrict__ gamma, const float* __restrict__ beta,
                       int l) {
    __shared__ float As[H2 * 66];       // transposed [k][n]
    __shared__ float scs[H2], sfs[H2];
    __shared__ float sred[8][HH];
    int tid = threadIdx.x;  // 128
    int n0 = blockIdx.x * 64;
    {   // tid == k
        float mu = g_sB[l][tid] * (1.f / NN);
        float var = g_qB[l][tid] * (1.f / NN) - mu * mu;
        float scr = gamma[tid] * rsqrtf(var + 1e-5f);
        scs[tid] = scr;
        sfs[tid] = beta[tid] - mu * scr;
    }
    __syncthreads();
    for (int idx = tid; idx < 64 * 32; idx += 128) {
        int r = idx >> 5, c4 = (idx & 31) * 4;
        int gn = n0 + r;
        float4 v = (gn < NN) ? *(const float4*)&g_hmid[gn * H2 + c4]
                             : make_float4(0.f, 0.f, 0.f, 0.f);
        As[(c4 + 0) * 66 + r] = fmaxf(v.x * scs[c4]     + sfs[c4],     0.f);
        As[(c4 + 1) * 66 + r] = fmaxf(v.y * scs[c4 + 1] + sfs[c4 + 1], 0.f);
        As[(c4 + 2) * 66 + r] = fmaxf(v.z * scs[c4 + 2] + sfs[c4 + 2], 0.f);
        As[(c4 + 3) * 66 + r] = fmaxf(v.w * scs[c4 + 3] + sfs[c4 + 3], 0.f);
    }
    __syncthreads();
    int tx = tid & 15, ty = tid >> 4;
    int col = tx * 4, row0 = ty * 8;
    u64 acc[4][4];
#pragma unroll
    for (int rp = 0; rp < 4; rp++)
#pragma unroll
        for (int c = 0; c < 4; c++) acc[rp][c] = 0ull;
#pragma unroll 4
    for (int k = 0; k < H2; k++) {
        u64 ap[4];
#pragma unroll
        for (int rp = 0; rp < 4; rp++)
            ap[rp] = *(const u64*)&As[k * 66 + row0 + rp * 2];
        float4 wv = *(const float4*)&w2[k * HH + col];
#pragma unroll
        for (int c = 0; c < 4; c++) {
            u32 wb = __float_as_uint(((const float*)&wv)[c]);
            u64 wd; PACK2(wd, wb, wb);
#pragma unroll
            for (int rp = 0; rp < 4; rp++) FMA2(acc[rp][c], ap[rp], wd);
        }
    }
    float4 bb = *(const float4*)&b2[col];
    float s[4] = {0.f, 0.f, 0.f, 0.f}, q[4] = {0.f, 0.f, 0.f, 0.f};
#pragma unroll
    for (int rp = 0; rp < 4; rp++) {
        float o0[4], o1[4];
#pragma unroll
        for (int c = 0; c < 4; c++) {
            u32 lo, hi; UNPACK2(lo, hi, acc[rp][c]);
            o0[c] = __uint_as_float(lo) + ((const float*)&bb)[c];
            o1[c] = __uint_as_float(hi) + ((const float*)&bb)[c];
        }
        int na = n0 + row0 + rp * 2;
        if (na < NN) {
            float4 h = *(const float4*)&g_h[na * HH + col];
            h.x += o0[0]; h.y += o0[1]; h.z += o0[2]; h.w += o0[3];
            *(float4*)&g_h[na * HH + col] = h;
            s[0] += h.x; s[1] += h.y; s[2] += h.z; s[3] += h.w;
            q[0] += h.x * h.x; q[1] += h.y * h.y; q[2] += h.z * h.z; q[3] += h.w * h.w;
        }
        if (na + 1 < NN) {
            float4 h = *(const float4*)&g_h[(na + 1) * HH + col];
            h.x += o1[0]; h.y += o1[1]; h.z += o1[2]; h.w += o1[3];
            *(float4*)&g_h[(na + 1) * HH + col] = h;
            s[0] += h.x; s[1] += h.y; s[2] += h.z; s[3] += h.w;
            q[0] += h.x * h.x; q[1] += h.y * h.y; q[2] += h.z * h.z; q[3] += h.w * h.w;
        }
    }
#pragma unroll
    for (int c = 0; c < 4; c++) sred[ty][col + c] = s[c];
    __syncthreads();
    if (tid < HH) {
        float S = 0.f;
#pragma unroll
        for (int i = 0; i < 8; i++) S += sred[i][tid];
        atomicAdd(&g_sA[l + 1][tid], S);
    }
    __syncthreads();
#pragma unroll
    for (int c = 0; c < 4; c++) sred[ty][col + c] = q[c];
    __syncthreads();
    if (tid < HH) {
        float Q = 0.f;
#pragma unroll
        for (int i = 0; i < 8; i++) Q += sred[i][tid];
        atomicAdd(&g_qA[l + 1][tid], Q);
    }
}

// ------- global mean pool + g_deg cleanup for next call -------
__global__ void k_pool(const int* __restrict__ batch) {
    int j = threadIdx.x;  // 64
    int zi = blockIdx.x * 64 + j;
    if (zi < NN) g_deg[zi] = 0;          // reset for next call
    int n0 = blockIdx.x * PCHUNK;
    if (n0 >= NN) return;
    int n1 = min(n0 + PCHUNK, NN);
    int cur = batch[n0];
    float s = 0.f, cnt = 0.f;
    for (int n = n0; n < n1; n++) {
        int b = batch[n];
        if (b != cur) {
            atomicAdd(&g_pool[cur * HH + j], s);
            if (j == 0) atomicAdd(&g_cnt[cur], cnt);
            s = 0.f; cnt = 0.f; cur = b;
        }
        s += g_h[n * HH + j];
        cnt += 1.f;
    }
    atomicAdd(&g_pool[cur * HH + j], s);
    if (j == 0) atomicAdd(&g_cnt[cur], cnt);
}

// ------- output + full accumulator cleanup for next call -------
__global__ void k_final(const float* __restrict__ W, const float* __restrict__ b,
                        float* __restrict__ out) {
    __shared__ float p[HH];
    int g = blockIdx.x, tid = threadIdx.x;  // 64 blocks x 64 threads
    float c = fmaxf(g_cnt[g], 1.f);
    p[tid] = fmaxf(g_pool[g * HH + tid] / c, 0.f);
    __syncthreads();
    // cleanup for next call (after reads)
    g_pool[g * HH + tid] = 0.f;
    if (tid == 0) { g_cnt[g] = 0.f; g_look[g] = 0ull; }
    int gi = g * 64 + tid;               // 0..4095
    if (gi < 3 * HH) { ((float*)g_sA)[gi] = 0.f; ((float*)g_qA)[gi] = 0.f; }
    if (gi < 2 * H2) { ((float*)g_sB)[gi] = 0.f; ((float*)g_qB)[gi] = 0.f; }
    if (tid < COUT) {
        float acc = b[tid];
#pragma unroll
        for (int k = 0; k < HH; k++) acc += p[k] * W[k * COUT + tid];
        out[g * COUT + tid] = acc;
    }
}

extern "C" void kernel_launch(void* const* d_in, const int* in_sizes, int n_in,
                              void* d_out, int out_size) {
    const float* x        = (const float*)d_in[0];
    const int*   ei       = (const int*)d_in[1];
    const float* ea       = (const float*)d_in[2];
    const int*   batch    = (const int*)d_in[3];
    const float* lin_in_w = (const float*)d_in[4];
    const float* lin_in_b = (const float*)d_in[5];
    const float* ng       = (const float*)d_in[6];
    const float* nb       = (const float*)d_in[7];
    const float* ew       = (const float*)d_in[8];
    const float* eb       = (const float*)d_in[9];
    const float* tt       = (const float*)d_in[10];
    const float* w1       = (const float*)d_in[11];
    const float* b1       = (const float*)d_in[12];
    const float* mg       = (const float*)d_in[13];
    const float* mb       = (const float*)d_in[14];
    const float* w2       = (const float*)d_in[15];
    const float* b2       = (const float*)d_in[16];
    const float* ow       = (const float*)d_in[17];
    const float* ob       = (const float*)d_in[18];
    float* out = (float*)d_out;

    k_histlin<<<HIST_BLKS + LIN_BLKS, 256>>>(ei, x, lin_in_w, lin_in_b);
    k_scan<<<SCAN_BLKS, 1024>>>(ng, nb);                 // scan + z0
    for (int l = 0; l < 2; l++) {
        k_embgemm<<<EE / 64, 256>>>(ei, ea, ew + l * EDIM * HH, eb + l * HH,
                                    l, ng + l * HH, nb + l * HH);  // +scatter l=0, +z1 l=1
        k_gathermlp1<<<(NN + 63) / 64, 256>>>(tt + l, w1 + l * HH * H2, b1 + l * H2, l);
        k_mlp2<<<(NN + 63) / 64, 128>>>(w2 + l * H2 * HH, b2 + l * HH,
                                        mg + l * H2, mb + l * H2, l);
    }
    k_pool<<<(NN + PCHUNK - 1) / PCHUNK, 64>>>(batch);
    k_final<<<GG, 64>>>(ow, ob, out);
}

// round 16
// speedup vs baseline: 1.4021x; 1.4021x over previous
#include <cuda_runtime.h>
#include <cuda_fp16.h>
#include <math.h>

#define NN   50000
#define EE   800000
#define FIN  32
#define HH   64
#define H2   128
#define EDIM 16
#define GG   64
#define COUT 40
#define PCHUNK 64
#define HIST_BLKS 782
#define LIN_BLKS 782        // 64-node tiles
#define ZBLKS 782           // embgemm blocks that also do the l=1 z-pass
#define SCAN_BLKS 49

typedef unsigned long long u64;
typedef unsigned int u32;

#define FMA2(acc, a, b) asm("fma.rn.f32x2 %0, %1, %2, %0;" : "+l"(acc) : "l"(a), "l"(b))
#define PACK2(d, lo, hi) asm("mov.b64 %0, {%1, %2};" : "=l"(d) : "r"(lo), "r"(hi))
#define UNPACK2(lo, hi, s) asm("mov.b64 {%0, %1}, %2;" : "=r"(lo), "=r"(hi) : "l"(s))

// ---------------- scratch (no allocation allowed) ----------------
// All mutable state is returned to zero by tail kernels (k_pool/k_final).
__device__ float g_h[NN * HH];      // node features (residual stream)
__device__ float g_z[NN * HH];      // relu(BN(h)) for current layer
__device__ float g_agg[NN * HH];    // softmax-agg output + root (MLP1 input)
__device__ float g_hmid[NN * H2];   // MLP hidden
__device__ float g_sA[3][HH];
__device__ float g_qA[3][HH];
__device__ float g_sB[2][H2];
__device__ float g_qB[2][H2];
__device__ float g_pool[GG * HH];
__device__ float g_cnt[GG];
// CSR scratch
__device__ int g_deg[NN];
__device__ int g_cur[NN];           // seeded with offsets by k_scan
__device__ int g_off[NN + 1];
__device__ int g_psrc[EE];
__device__ int g_perm[EE];          // edge e -> CSR slot (written by embgemm l=0)
__device__ u32 g_embh[(size_t)EE * 32];      // current layer's edge emb (CSR order), half2
__device__ u64 g_look[64];

// -------- merged: degree histogram (blocks [0,782)) + input linear ---------
// linear part: f32x2 register-tiled GEMM h = x @ W_in + b, fused statsA(0)
__global__ void k_histlin(const int* __restrict__ ei,
                          const float* __restrict__ x,
                          const float* __restrict__ W,
                          const float* __restrict__ b) {
    __shared__ float xs[FIN * 68];        // transposed [k][node], pad 68
    __shared__ float sred[16][HH];        // 4KB
    int tid = threadIdx.x;

    if (blockIdx.x < HIST_BLKS) {         // ---- histogram part ----
        int t = blockIdx.x * 256 + tid;
        if (t * 4 < EE) {
            int4 d4 = ((const int4*)(ei + EE))[t];
            atomicAdd(&g_deg[d4.x], 1);
            atomicAdd(&g_deg[d4.y], 1);
            atomicAdd(&g_deg[d4.z], 1);
            atomicAdd(&g_deg[d4.w], 1);
        }
        return;
    }
    // ---- input linear: 64-node tile, f32x2 ----
    int bid = blockIdx.x - HIST_BLKS;
    int n0 = bid * 64;
    for (int idx = tid; idx < 64 * 8; idx += 256) {
        int r = idx >> 3, q = idx & 7;
        int gn = n0 + r;
        float4 v = (gn < NN) ? ((const float4*)(x + (size_t)gn * FIN))[q]
                             : make_float4(0.f, 0.f, 0.f, 0.f);
        xs[(q * 4 + 0) * 68 + r] = v.x;
        xs[(q * 4 + 1) * 68 + r] = v.y;
        xs[(q * 4 + 2) * 68 + r] = v.z;
        xs[(q * 4 + 3) * 68 + r] = v.w;
    }
    __syncthreads();
    int tx = tid & 15, ty = tid >> 4;     // col quarter (16), row group (16)
    int col = tx * 4, row0 = ty * 4;
    u64 acc[2][4];
#pragma unroll
    for (int p = 0; p < 2; p++)
#pragma unroll
        for (int c = 0; c < 4; c++) acc[p][c] = 0ull;
#pragma unroll 4
    for (int k = 0; k < FIN; k++) {
        ulonglong2 ap = *(const ulonglong2*)&xs[k * 68 + row0];
        float4 wv = *(const float4*)&W[k * HH + col];
#pragma unroll
        for (int c = 0; c < 4; c++) {
            u32 wb = __float_as_uint(((const float*)&wv)[c]);
            u64 wd; PACK2(wd, wb, wb);
            FMA2(acc[0][c], ap.x, wd);
            FMA2(acc[1][c], ap.y, wd);
        }
    }
    float4 bb = *(const float4*)&b[col];
    float s[4] = {0.f, 0.f, 0.f, 0.f}, q[4] = {0.f, 0.f, 0.f, 0.f};
#pragma unroll
    for (int p = 0; p < 2; p++) {
        float o0[4], o1[4];
#pragma unroll
        for (int c = 0; c < 4; c++) {
            u32 l_, h_; UNPACK2(l_, h_, acc[p][c]);
            o0[c] = __uint_as_float(l_) + ((const float*)&bb)[c];
            o1[c] = __uint_as_float(h_) + ((const float*)&bb)[c];
        }
        int na = n0 + row0 + p * 2;
        if (na < NN) {
            *(float4*)&g_h[na * HH + col] = make_float4(o0[0], o0[1], o0[2], o0[3]);
#pragma unroll
            for (int c = 0; c < 4; c++) { s[c] += o0[c]; q[c] += o0[c] * o0[c]; }
        }
        if (na + 1 < NN) {
            *(float4*)&g_h[(na + 1) * HH + col] = make_float4(o1[0], o1[1], o1[2], o1[3]);
#pragma unroll
            for (int c = 0; c < 4; c++) { s[c] += o1[c]; q[c] += o1[c] * o1[c]; }
        }
    }
#pragma unroll
    for (int c = 0; c < 4; c++) sred[ty][col + c] = s[c];
    __syncthreads();
    if (tid < HH) {
        float S = 0.f;
#pragma unroll
        for (int i = 0; i < 16; i++) S += sred[i][tid];
        atomicAdd(&g_sA[0][tid], S);
    }
    __syncthreads();
#pragma unroll
    for (int c = 0; c < 4; c++) sred[ty][col + c] = q[c];
    __syncthreads();
    if (tid < HH) {
        float Q = 0.f;
#pragma unroll
        for (int i = 0; i < 16; i++) Q += sred[i][tid];
        atomicAdd(&g_qA[0][tid], Q);
    }
}

// scan with decoupled lookback; seeds g_cur; then computes z0 = relu(BN(h))
__global__ void k_scan(const float* __restrict__ gamma, const float* __restrict__ beta) {
    __shared__ int sh[1024];
    __shared__ int exc_sh;
    __shared__ float scz[HH], sfz[HH];
    int b = blockIdx.x, t = threadIdx.x;
    int i = b * 1024 + t;
    int v = (i < NN) ? g_deg[i] : 0;
    sh[t] = v;
    __syncthreads();
    for (int off = 1; off < 1024; off <<= 1) {
        int u = (t >= off) ? sh[t - off] : 0;
        __syncthreads();
        sh[t] += u;
        __syncthreads();
    }
    int total = sh[1023];
    if (t == 0) {
        const u64 FA = 1ull << 62, FP = 2ull << 62;
        if (b == 0) {
            atomicExch(&g_look[0], FP | (u32)total);
            exc_sh = 0;
        } else {
            atomicExch(&g_look[b], FA | (u32)total);
            int run = 0, j = b - 1;
            while (1) {
                u64 s = atomicAdd(&g_look[j], 0ull);
                u64 f = s >> 62;
                if (f == 0) continue;
                int val = (int)(s & 0xFFFFFFFFull);
                run += val;
                if (f == 2) break;
                j--;
            }
            atomicExch(&g_look[b], FP | (u32)(run + total));
            exc_sh = run;
        }
    }
    if (t < HH) {           // BN consts for layer 0 (stats ready from histlin)
        float mu = g_sA[0][t] * (1.f / NN);
        float var = g_qA[0][t] * (1.f / NN) - mu * mu;
        float s = gamma[t] * rsqrtf(var + 1e-5f);
        scz[t] = s;
        sfz[t] = beta[t] - mu * s;
    }
    __syncthreads();
    int e = exc_sh;
    if (i < NN) {
        int off = e + sh[t] - v;   // exclusive
        g_off[i] = off;
        g_cur[i] = off;            // seed for bump allocation in embgemm l=0
    }
    if (b == 0 && t == 0) g_off[NN] = EE;
    // z0 pass, float4 grid-stride
    for (int i4 = b * 1024 + t; i4 < NN * HH / 4; i4 += SCAN_BLKS * 1024) {
        int j = (i4 * 4) & 63;
        float4 h4 = ((const float4*)g_h)[i4];
        float4 o;
        o.x = fmaxf(h4.x * scz[j]     + sfz[j],     0.f);
        o.y = fmaxf(h4.y * scz[j + 1] + sfz[j + 1], 0.f);
        o.z = fmaxf(h4.z * scz[j + 2] + sfz[j + 2], 0.f);
        o.w = fmaxf(h4.w * scz[j + 3] + sfz[j + 3], 0.f);
        ((float4*)g_z)[i4] = o;
    }
}

// ------- edge-emb GEMM (+ fused scatter when l==0) -------------------------
// l==0: 64 threads/tile allocate CSR slots (atomicAdd), write psrc & perm
// l==1: reload slots from perm; first ZBLKS blocks also compute z1
__global__ void k_embgemm(const int* __restrict__ ei, const float* __restrict__ ea,
                          const float* __restrict__ W, const float* __restrict__ bias,
                          int l, const float* __restrict__ gamma,
                          const float* __restrict__ beta) {
    __shared__ float As[16 * 68];       // transposed [k][edge], pad 68 (16B aligned)
    __shared__ int idxs[64];
    int tid = threadIdx.x;  // 256
    int e0 = blockIdx.x * 64;
    if (l == 0) {
        if (tid < 64) {                 // ---- fused scatter ----
            int e = e0 + tid;
            int src = __ldg(&ei[e]);
            int d = __ldg(&ei[EE + e]);
            int idx = atomicAdd(&g_cur[d], 1);
            g_psrc[idx] = src;
            g_perm[e] = idx;
            idxs[tid] = idx;
        }
    } else {
        if (tid < 64) idxs[tid] = g_perm[e0 + tid];
    }
    {
        int r = tid >> 2, q = tid & 3;  // 64 edges x 4 quarters
        float4 v = ((const float4*)(ea + (size_t)(e0 + r) * EDIM))[q];
        As[(q * 4 + 0) * 68 + r] = v.x;
        As[(q * 4 + 1) * 68 + r] = v.y;
        As[(q * 4 + 2) * 68 + r] = v.z;
        As[(q * 4 + 3) * 68 + r] = v.w;
    }
    __syncthreads();
    int tx = tid & 15, ty = tid >> 4;   // col quarter, edge group
    int col = tx * 4, row0 = ty * 4;
    u64 acc[2][4];
#pragma unroll
    for (int p = 0; p < 2; p++)
#pragma unroll
        for (int c = 0; c < 4; c++) acc[p][c] = 0ull;
#pragma unroll
    for (int k = 0; k < EDIM; k++) {
        ulonglong2 ap = *(const ulonglong2*)&As[k * 68 + row0];  // LDS.128
        float4 wv = *(const float4*)&W[k * HH + col];
#pragma unroll
        for (int c = 0; c < 4; c++) {
            u32 wb = __float_as_uint(((const float*)&wv)[c]);
            u64 wd; PACK2(wd, wb, wb);
            FMA2(acc[0][c], ap.x, wd);
            FMA2(acc[1][c], ap.y, wd);
        }
    }
    float4 bb = *(const float4*)&bias[col];
    int dst[4] = {idxs[row0], idxs[row0 + 1], idxs[row0 + 2], idxs[row0 + 3]};
#pragma unroll
    for (int p = 0; p < 2; p++) {
        float lo[4], hi[4];
#pragma unroll
        for (int c = 0; c < 4; c++) {
            u32 l_, h_; UNPACK2(l_, h_, acc[p][c]);
            lo[c] = __uint_as_float(l_) + ((const float*)&bb)[c];
            hi[c] = __uint_as_float(h_) + ((const float*)&bb)[c];
        }
        __half2 a01 = __floats2half2_rn(lo[0], lo[1]);
        __half2 a23 = __floats2half2_rn(lo[2], lo[3]);
        u64 w0; PACK2(w0, *(u32*)&a01, *(u32*)&a23);
        ((u64*)(g_embh + (size_t)dst[p * 2] * 32))[tx] = w0;
        __half2 b01 = __floats2half2_rn(hi[0], hi[1]);
        __half2 b23 = __floats2half2_rn(hi[2], hi[3]);
        u64 w1; PACK2(w1, *(u32*)&b01, *(u32*)&b23);
        ((u64*)(g_embh + (size_t)dst[p * 2 + 1] * 32))[tx] = w1;
    }
    // ---- z1 pass for layer 1 (uniform per-block condition) ----
    if (l == 1 && blockIdx.x < ZBLKS) {
        __shared__ float scz[HH], sfz[HH];
        if (tid < HH) {
            float mu = g_sA[1][tid] * (1.f / NN);
            float var = g_qA[1][tid] * (1.f / NN) - mu * mu;
            float s = gamma[tid] * rsqrtf(var + 1e-5f);
            scz[tid] = s;
            sfz[tid] = beta[tid] - mu * s;
        }
        __syncthreads();
        int n0z = blockIdx.x * 64;
        for (int idx = tid; idx < 64 * 16; idx += 256) {
            int r = idx >> 4, c4 = (idx & 15) * 4;
            int n = n0z + r;
            if (n < NN) {
                float4 v = *(const float4*)&g_h[n * HH + c4];
                float4 o;
                o.x = fmaxf(v.x * scz[c4]     + sfz[c4],     0.f);
                o.y = fmaxf(v.y * scz[c4 + 1] + sfz[c4 + 1], 0.f);
                o.z = fmaxf(v.z * scz[c4 + 2] + sfz[c4 + 2], 0.f);
                o.w = fmaxf(v.w * scz[c4 + 3] + sfz[c4 + 3], 0.f);
                *(float4*)&g_z[n * HH + c4] = o;
            }
        }
    }
}

// ------- light CSR-gather, 8-edge batched loads for MLP=8 ------------------
// one warp per node; lane owns features (2*lane, 2*lane+1)
__global__ void k_gather(const float* __restrict__ tptr) {
    int tid = threadIdx.x;
    int lane = tid & 31;
    int n = (blockIdx.x * blockDim.x + tid) >> 5;
    if (n >= NN) return;
    float tc2 = tptr[0] * 1.4426950408889634f;   // fold log2(e) into temperature
    int j0 = lane * 2;
    int beg = g_off[n], end = g_off[n + 1];
    float den0 = 0.f, num0 = 0.f, den1 = 0.f, num1 = 0.f;
    int i = beg;
    for (; i + 8 <= end; i += 8) {
        int srcs[8]; u32 ehb[8];
#pragma unroll
        for (int u = 0; u < 8; u++) srcs[u] = g_psrc[i + u];
#pragma unroll
        for (int u = 0; u < 8; u++) ehb[u] = g_embh[(size_t)(i + u) * 32 + lane];
        float2 zs[8];
#pragma unroll
        for (int u = 0; u < 8; u++) zs[u] = *(const float2*)&g_z[srcs[u] * HH + j0];
#pragma unroll
        for (int u = 0; u < 8; u++) {
            float2 emb = __half22float2(*(__half2*)&ehb[u]);
            float m0 = fmaxf(zs[u].x + emb.x, 0.f) + 1e-7f;
            float m1 = fmaxf(zs[u].y + emb.y, 0.f) + 1e-7f;
            float ex0 = exp2f(m0 * tc2);   // no max-shift: m in [1e-7, ~6]
            float ex1 = exp2f(m1 * tc2);
            den0 += ex0; num0 += ex0 * m0;
            den1 += ex1; num1 += ex1 * m1;
        }
    }
    for (; i < end; i++) {
        int src = g_psrc[i];
        u32 ehb = g_embh[(size_t)i * 32 + lane];
        float2 emb = __half22float2(*(__half2*)&ehb);
        float2 z = *(const float2*)&g_z[src * HH + j0];
        float m0 = fmaxf(z.x + emb.x, 0.f) + 1e-7f;
        float m1 = fmaxf(z.y + emb.y, 0.f) + 1e-7f;
        float ex0 = exp2f(m0 * tc2);
        float ex1 = exp2f(m1 * tc2);
        den0 += ex0; num0 += ex0 * m0;
        den1 += ex1; num1 += ex1 * m1;
    }
    float2 zr = *(const float2*)&g_z[n * HH + j0];
    float a0 = num0 / (den0 + 1e-16f) + zr.x;
    float a1 = num1 / (den1 + 1e-16f) + zr.y;
    *(float2*)&g_agg[n * HH + j0] = make_float2(a0, a1);
}

// ------- MLP1 GEMM, f32x2 packed: g_hmid[N,128] = g_agg[N,64] @ w1 + b1 -----
__global__ void k_mlp1(const float* __restrict__ w1, const float* __restrict__ b1, int l) {
    __shared__ float As[64 * 66];       // transposed [k][n]
    __shared__ float sred[8][H2];
    int tid = threadIdx.x;  // 256
    int n0 = blockIdx.x * 64;
    for (int idx = tid; idx < 64 * 16; idx += 256) {
        int r = idx >> 4, c4 = (idx & 15) * 4;
        int gn = n0 + r;
        float4 v = (gn < NN) ? *(const float4*)&g_agg[gn * HH + c4]
                             : make_float4(0.f, 0.f, 0.f, 0.f);
        As[(c4 + 0) * 66 + r] = v.x;
        As[(c4 + 1) * 66 + r] = v.y;
        As[(c4 + 2) * 66 + r] = v.z;
        As[(c4 + 3) * 66 + r] = v.w;
    }
    __syncthreads();
    int tx = tid & 31, ty = tid >> 5;
    int col = tx * 4, row0 = ty * 8;
    u64 acc[4][4];
#pragma unroll
    for (int rp = 0; rp < 4; rp++)
#pragma unroll
        for (int c = 0; c < 4; c++) acc[rp][c] = 0ull;
#pragma unroll 4
    for (int k = 0; k < 64; k++) {
        u64 ap[4];
#pragma unroll
        for (int rp = 0; rp < 4; rp++)
            ap[rp] = *(const u64*)&As[k * 66 + row0 + rp * 2];
        float4 wv = *(const float4*)&w1[k * H2 + col];
#pragma unroll
        for (int c = 0; c < 4; c++) {
            u32 wb = __float_as_uint(((const float*)&wv)[c]);
            u64 wd; PACK2(wd, wb, wb);
#pragma unroll
            for (int rp = 0; rp < 4; rp++) FMA2(acc[rp][c], ap[rp], wd);
        }
    }
    float4 bb = *(const float4*)&b1[col];
    float s[4] = {0.f, 0.f, 0.f, 0.f}, q[4] = {0.f, 0.f, 0.f, 0.f};
#pragma unroll
    for (int rp = 0; rp < 4; rp++) {
        float o0[4], o1[4];
#pragma unroll
        for (int c = 0; c < 4; c++) {
            u32 lo, hi; UNPACK2(lo, hi, acc[rp][c]);
            o0[c] = __uint_as_float(lo) + ((const float*)&bb)[c];
            o1[c] = __uint_as_float(hi) + ((const float*)&bb)[c];
        }
        int na = n0 + row0 + rp * 2;
        if (na < NN) {
            *(float4*)&g_hmid[na * H2 + col] = make_float4(o0[0], o0[1], o0[2], o0[3]);
#pragma unroll
            for (int c = 0; c < 4; c++) { s[c] += o0[c]; q[c] += o0[c] * o0[c]; }
        }
        if (na + 1 < NN) {
            *(float4*)&g_hmid[(na + 1) * H2 + col] = make_float4(o1[0], o1[1], o1[2], o1[3]);
#pragma unroll
            for (int c = 0; c < 4; c++) { s[c] += o1[c]; q[c] += o1[c] * o1[c]; }
        }
    }
#pragma unroll
    for (int c = 0; c < 4; c++) sred[ty][col + c] = s[c];
    __syncthreads();
    if (tid < H2) {
        float S = 0.f;
#pragma unroll
        for (int i = 0; i < 8; i++) S += sred[i][tid];
        atomicAdd(&g_sB[l][tid], S);
    }
    __syncthreads();
#pragma unroll
    for (int c = 0; c < 4; c++) sred[ty][col + c] = q[c];
    __syncthreads();
    if (tid < H2) {
        float Q = 0.f;
#pragma unroll
        for (int i = 0; i < 8; i++) Q += sred[i][tid];
        atomicAdd(&g_qB[l][tid], Q);
    }
}

// ------- MLP2 GEMM (128 thr), fused BN2+ReLU staging + residual ------------
__global__ void k_mlp2(const float* __restrict__ w2, const float* __restrict__ b2,
                       const float* __restrict__ gamma, const float* __restrict__ beta,
                       int l) {
    __shared__ float As[H2 * 66];       // transposed [k][n]
    __shared__ float scs[H2], sfs[H2];
    __shared__ float sred[8][HH];
    int tid = threadIdx.x;  // 128
    int n0 = blockIdx.x * 64;
    {   // tid == k
        float mu = g_sB[l][tid] * (1.f / NN);
        float var = g_qB[l][tid] * (1.f / NN) - mu * mu;
        float scr = gamma[tid] * rsqrtf(var + 1e-5f);
        scs[tid] = scr;
        sfs[tid] = beta[tid] - mu * scr;
    }
    __syncthreads();
    for (int idx = tid; idx < 64 * 32; idx += 128) {
        int r = idx >> 5, c4 = (idx & 31) * 4;
        int gn = n0 + r;
        float4 v = (gn < NN) ? *(const float4*)&g_hmid[gn * H2 + c4]
                             : make_float4(0.f, 0.f, 0.f, 0.f);
        As[(c4 + 0) * 66 + r] = fmaxf(v.x * scs[c4]     + sfs[c4],     0.f);
        As[(c4 + 1) * 66 + r] = fmaxf(v.y * scs[c4 + 1] + sfs[c4 + 1], 0.f);
        As[(c4 + 2) * 66 + r] = fmaxf(v.z * scs[c4 + 2] + sfs[c4 + 2], 0.f);
        As[(c4 + 3) * 66 + r] = fmaxf(v.w * scs[c4 + 3] + sfs[c4 + 3], 0.f);
    }
    __syncthreads();
    int tx = tid & 15, ty = tid >> 4;
    int col = tx * 4, row0 = ty * 8;
    u64 acc[4][4];
#pragma unroll
    for (int rp = 0; rp < 4; rp++)
#pragma unroll
        for (int c = 0; c < 4; c++) acc[rp][c] = 0ull;
#pragma unroll 4
    for (int k = 0; k < H2; k++) {
        u64 ap[4];
#pragma unroll
        for (int rp = 0; rp < 4; rp++)
            ap[rp] = *(const u64*)&As[k * 66 + row0 + rp * 2];
        float4 wv = *(const float4*)&w2[k * HH + col];
#pragma unroll
        for (int c = 0; c < 4; c++) {
            u32 wb = __float_as_uint(((const float*)&wv)[c]);
            u64 wd; PACK2(wd, wb, wb);
#pragma unroll
            for (int rp = 0; rp < 4; rp++) FMA2(acc[rp][c], ap[rp], wd);
        }
    }
    float4 bb = *(const float4*)&b2[col];
    float s[4] = {0.f, 0.f, 0.f, 0.f}, q[4] = {0.f, 0.f, 0.f, 0.f};
#pragma unroll
    for (int rp = 0; rp < 4; rp++) {
        float o0[4], o1[4];
#pragma unroll
        for (int c = 0; c < 4; c++) {
            u32 lo, hi; UNPACK2(lo, hi, acc[rp][c]);
            o0[c] = __uint_as_float(lo) + ((const float*)&bb)[c];
            o1[c] = __uint_as_float(hi) + ((const float*)&bb)[c];
        }
        int na = n0 + row0 + rp * 2;
        if (na < NN) {
            float4 h = *(const float4*)&g_h[na * HH + col];
            h.x += o0[0]; h.y += o0[1]; h.z += o0[2]; h.w += o0[3];
            *(float4*)&g_h[na * HH + col] = h;
            s[0] += h.x; s[1] += h.y; s[2] += h.z; s[3] += h.w;
            q[0] += h.x * h.x; q[1] += h.y * h.y; q[2] += h.z * h.z; q[3] += h.w * h.w;
        }
        if (na + 1 < NN) {
            float4 h = *(const float4*)&g_h[(na + 1) * HH + col];
            h.x += o1[0]; h.y += o1[1]; h.z += o1[2]; h.w += o1[3];
            *(float4*)&g_h[(na + 1) * HH + col] = h;
            s[0] += h.x; s[1] += h.y; s[2] += h.z; s[3] += h.w;
            q[0] += h.x * h.x; q[1] += h.y * h.y; q[2] += h.z * h.z; q[3] += h.w * h.w;
        }
    }
#pragma unroll
    for (int c = 0; c < 4; c++) sred[ty][col + c] = s[c];
    __syncthreads();
    if (tid < HH) {
        float S = 0.f;
#pragma unroll
        for (int i = 0; i < 8; i++) S += sred[i][tid];
        atomicAdd(&g_sA[l + 1][tid], S);
    }
    __syncthreads();
#pragma unroll
    for (int c = 0; c < 4; c++) sred[ty][col + c] = q[c];
    __syncthreads();
    if (tid < HH) {
        float Q = 0.f;
#pragma unroll
        for (int i = 0; i < 8; i++) Q += sred[i][tid];
        atomicAdd(&g_qA[l + 1][tid], Q);
    }
}

// ------- global mean pool + g_deg cleanup for next call -------
__global__ void k_pool(const int* __restrict__ batch) {
    int j = threadIdx.x;  // 64
    int zi = blockIdx.x * 64 + j;
    if (zi < NN) g_deg[zi] = 0;          // reset for next call
    int n0 = blockIdx.x * PCHUNK;
    if (n0 >= NN) return;
    int n1 = min(n0 + PCHUNK, NN);
    int cur = batch[n0];
    float s = 0.f, cnt = 0.f;
    for (int n = n0; n < n1; n++) {
        int b = batch[n];
        if (b != cur) {
            atomicAdd(&g_pool[cur * HH + j], s);
            if (j == 0) atomicAdd(&g_cnt[cur], cnt);
            s = 0.f; cnt = 0.f; cur = b;
        }
        s += g_h[n * HH + j];
        cnt += 1.f;
    }
    atomicAdd(&g_pool[cur * HH + j], s);
    if (j == 0) atomicAdd(&g_cnt[cur], cnt);
}

// ------- output + full accumulator cleanup for next call -------
__global__ void k_final(const float* __restrict__ W, const float* __restrict__ b,
                        float* __restrict__ out) {
    __shared__ float p[HH];
    int g = blockIdx.x, tid = threadIdx.x;  // 64 blocks x 64 threads
    float c = fmaxf(g_cnt[g], 1.f);
    p[tid] = fmaxf(g_pool[g * HH + tid] / c, 0.f);
    __syncthreads();
    // cleanup for next call (after reads)
    g_pool[g * HH + tid] = 0.f;
    if (tid == 0) { g_cnt[g] = 0.f; g_look[g] = 0ull; }
    int gi = g * 64 + tid;               // 0..4095
    if (gi < 3 * HH) { ((float*)g_sA)[gi] = 0.f; ((float*)g_qA)[gi] = 0.f; }
    if (gi < 2 * H2) { ((float*)g_sB)[gi] = 0.f; ((float*)g_qB)[gi] = 0.f; }
    if (tid < COUT) {
        float acc = b[tid];
#pragma unroll
        for (int k = 0; k < HH; k++) acc += p[k] * W[k * COUT + tid];
        out[g * COUT + tid] = acc;
    }
}

extern "C" void kernel_launch(void* const* d_in, const int* in_sizes, int n_in,
                              void* d_out, int out_size) {
    const float* x        = (const float*)d_in[0];
    const int*   ei       = (const int*)d_in[1];
    const float* ea       = (const float*)d_in[2];
    const int*   batch    = (const int*)d_in[3];
    const float* lin_in_w = (const float*)d_in[4];
    const float* lin_in_b = (const float*)d_in[5];
    const float* ng       = (const float*)d_in[6];
    const float* nb       = (const float*)d_in[7];
    const float* ew       = (const float*)d_in[8];
    const float* eb       = (const float*)d_in[9];
    const float* tt       = (const float*)d_in[10];
    const float* w1       = (const float*)d_in[11];
    const float* b1       = (const float*)d_in[12];
    const float* mg       = (const float*)d_in[13];
    const float* mb       = (const float*)d_in[14];
    const float* w2       = (const float*)d_in[15];
    const float* b2       = (const float*)d_in[16];
    const float* ow       = (const float*)d_in[17];
    const float* ob       = (const float*)d_in[18];
    float* out = (float*)d_out;

    k_histlin<<<HIST_BLKS + LIN_BLKS, 256>>>(ei, x, lin_in_w, lin_in_b);
    k_scan<<<SCAN_BLKS, 1024>>>(ng, nb);                 // scan + z0
    for (int l = 0; l < 2; l++) {
        k_embgemm<<<EE / 64, 256>>>(ei, ea, ew + l * EDIM * HH, eb + l * HH,
                                    l, ng + l * HH, nb + l * HH);  // +scatter l=0, +z1 l=1
        k_gather<<<(NN * 32 + 255) / 256, 256>>>(tt + l);
        k_mlp1<<<(NN + 63) / 64, 256>>>(w1 + l * HH * H2, b1 + l * H2, l);
        k_mlp2<<<(NN + 63) / 64, 128>>>(w2 + l * H2 * HH, b2 + l * HH,
                                        mg + l * H2, mb + l * H2, l);
    }
    k_pool<<<(NN + PCHUNK - 1) / PCHUNK, 64>>>(batch);
    k_final<<<GG, 64>>>(ow, ob, out);
}